// round 12
// baseline (speedup 1.0000x reference)
#include <cuda_runtime.h>
#include <cstdint>

#define DIM        2048
#define NE         64
#define M_TOTAL    32768      // 4 * 8192
#define BM         64
#define BK         32
#define NTHREADS   256
#define NBLOCKS    (M_TOTAL / BM)   // 512
#define NTILES     (DIM / BK)       // 64
#define AS_STRIDE  66         // A tile row stride (floats): 2-way STS banks, 8B-aligned LDS
#define BS_STRIDE  68         // B tile row stride (floats): 16B-aligned LDS.128
#define SC_STRIDE  65         // scores row stride (floats) -> conflict-free

// Deterministic per-block partial softmax-prob sums (no atomics on data).
__device__ float g_partial[NBLOCKS][NE];
__device__ unsigned int g_count = 0;   // ticket counter; last block resets -> replay-safe

// out layout (float32): [0,65536) indices, [65536,131072) weights, [131072] aux
#define OUT_W_OFF  (M_TOTAL * 2)
#define OUT_AUX    (M_TOTAL * 4)

typedef unsigned long long u64;

__device__ __forceinline__ u64 pack2(float v) {
    u64 r;
    asm("mov.b64 %0, {%1, %1};" : "=l"(r) : "f"(v));
    return r;
}

__device__ __forceinline__ void fma2(u64& acc, u64 a, u64 b) {
    asm("fma.rn.f32x2 %0, %1, %2, %0;" : "+l"(acc) : "l"(a), "l"(b));
}

__global__ __launch_bounds__(NTHREADS)
void router_main(const float* __restrict__ x,
                 const float* __restrict__ W,
                 float* __restrict__ out) {
    // smem union: GEMM tiles (As 32x66 + Bs 32x68 = 16.8KB) then scores (64x65 = 16.3KB)
    __shared__ float sm[BK * AS_STRIDE + BK * BS_STRIDE];   // 4288 floats = 17152 B
    __shared__ float s_rowmax[BM];
    __shared__ float s_rowinv[BM];
    __shared__ float s_p2[4][NE];
    __shared__ unsigned int s_rank;

    float* As = sm;                       // [BK][AS_STRIDE]  k-major, m contiguous
    float* Bs = sm + BK * AS_STRIDE;      // [BK][BS_STRIDE]  k-major, e contiguous
    float* scores = sm;                   // [BM][SC_STRIDE] unions over tiles (16640 B < 17152 B)

    const int tid = threadIdx.x;
    const int tx  = tid & 15;             // expert group: 4 experts (tx*4 .. tx*4+3)
    const int ty  = tid >> 4;             // row group: 4 rows = 2 row-pairs

    // G2S index maps (fixed per thread)
    // A tile: 64 rows x 32 k = 512 float4 -> 2 per thread
    int aRow[2], aKq[2];
#pragma unroll
    for (int i = 0; i < 2; i++) {
        int idx = tid + i * NTHREADS;
        aRow[i] = idx >> 3;
        aKq[i]  = idx & 7;
    }
    // B tile: 64 experts x 32 k = 512 float4 -> 2 per thread
    int bEr[2], bKq[2];
#pragma unroll
    for (int i = 0; i < 2; i++) {
        int idx = tid + i * NTHREADS;
        bEr[i] = idx >> 3;
        bKq[i] = idx & 7;
    }

    const float* xblk = x + (size_t)blockIdx.x * BM * DIM;

    // acc[pair i][expert j] : packed f32x2 over rows {ty*4+2i, ty*4+2i+1}
    u64 acc[2][4];
#pragma unroll
    for (int i = 0; i < 2; i++)
#pragma unroll
        for (int j = 0; j < 4; j++) acc[i][j] = 0ULL;

    float4 aReg[2], bReg[2];

    // ---- prologue: load tile 0 into registers, store to smem ----
#pragma unroll
    for (int i = 0; i < 2; i++)
        aReg[i] = *reinterpret_cast<const float4*>(xblk + (size_t)aRow[i] * DIM + aKq[i] * 4);
#pragma unroll
    for (int i = 0; i < 2; i++)
        bReg[i] = *reinterpret_cast<const float4*>(W + (size_t)bEr[i] * DIM + bKq[i] * 4);

#pragma unroll
    for (int i = 0; i < 2; i++) {
        int kb = aKq[i] * 4;
        As[(kb + 0) * AS_STRIDE + aRow[i]] = aReg[i].x;
        As[(kb + 1) * AS_STRIDE + aRow[i]] = aReg[i].y;
        As[(kb + 2) * AS_STRIDE + aRow[i]] = aReg[i].z;
        As[(kb + 3) * AS_STRIDE + aRow[i]] = aReg[i].w;
    }
#pragma unroll
    for (int i = 0; i < 2; i++) {
        int kb = bKq[i] * 4;
        Bs[(kb + 0) * BS_STRIDE + bEr[i]] = bReg[i].x;
        Bs[(kb + 1) * BS_STRIDE + bEr[i]] = bReg[i].y;
        Bs[(kb + 2) * BS_STRIDE + bEr[i]] = bReg[i].z;
        Bs[(kb + 3) * BS_STRIDE + bEr[i]] = bReg[i].w;
    }
    __syncthreads();

#pragma unroll 1
    for (int t = 0; t < NTILES; t++) {
        const bool more = t + 1 < NTILES;
        // ---- prefetch next tile into registers (LDGs overlap compute) ----
        if (more) {
            int kn = (t + 1) * BK;
#pragma unroll
            for (int i = 0; i < 2; i++)
                aReg[i] = *reinterpret_cast<const float4*>(xblk + (size_t)aRow[i] * DIM + kn + aKq[i] * 4);
#pragma unroll
            for (int i = 0; i < 2; i++)
                bReg[i] = *reinterpret_cast<const float4*>(W + (size_t)bEr[i] * DIM + kn + bKq[i] * 4);
        }

        // ---- compute current tile ----
#pragma unroll
        for (int kk = 0; kk < BK; kk++) {
            const u64* ar = reinterpret_cast<const u64*>(As + kk * AS_STRIDE + ty * 4);
            u64 a0 = ar[0], a1 = ar[1];
            float4 bv = *reinterpret_cast<const float4*>(Bs + kk * BS_STRIDE + tx * 4);
            u64 b0 = pack2(bv.x);
            u64 b1 = pack2(bv.y);
            u64 b2 = pack2(bv.z);
            u64 b3 = pack2(bv.w);
            fma2(acc[0][0], a0, b0); fma2(acc[0][1], a0, b1);
            fma2(acc[0][2], a0, b2); fma2(acc[0][3], a0, b3);
            fma2(acc[1][0], a1, b0); fma2(acc[1][1], a1, b1);
            fma2(acc[1][2], a1, b2); fma2(acc[1][3], a1, b3);
        }
        __syncthreads();   // everyone done READING this tile

        // ---- store prefetched tile ----
        if (more) {
#pragma unroll
            for (int i = 0; i < 2; i++) {
                int kb = aKq[i] * 4;
                As[(kb + 0) * AS_STRIDE + aRow[i]] = aReg[i].x;
                As[(kb + 1) * AS_STRIDE + aRow[i]] = aReg[i].y;
                As[(kb + 2) * AS_STRIDE + aRow[i]] = aReg[i].z;
                As[(kb + 3) * AS_STRIDE + aRow[i]] = aReg[i].w;
            }
#pragma unroll
            for (int i = 0; i < 2; i++) {
                int kb = bKq[i] * 4;
                Bs[(kb + 0) * BS_STRIDE + bEr[i]] = bReg[i].x;
                Bs[(kb + 1) * BS_STRIDE + bEr[i]] = bReg[i].y;
                Bs[(kb + 2) * BS_STRIDE + bEr[i]] = bReg[i].z;
                Bs[(kb + 3) * BS_STRIDE + bEr[i]] = bReg[i].w;
            }
            __syncthreads();   // tile visible before next compute
        }
    }

    // ---- scatter scores into smem [64][65] ----
#pragma unroll
    for (int i = 0; i < 2; i++) {
        int row0 = ty * 4 + 2 * i;
#pragma unroll
        for (int j = 0; j < 4; j++) {
            int e = tx * 4 + j;
            u64 p = acc[i][j];
            float lo = __uint_as_float((unsigned)(p & 0xffffffffULL));
            float hi = __uint_as_float((unsigned)(p >> 32));
            scores[row0 * SC_STRIDE + e]       = lo;
            scores[(row0 + 1) * SC_STRIDE + e] = hi;
        }
    }
    __syncthreads();

    // ---- phase 1: per-row top-2, weights, row softmax stats ----
    if (tid < BM) {
        const float* srow = scores + tid * SC_STRIDE;
        float v0 = -3.4e38f, v1 = -3.4e38f;
        int i0 = 0, i1 = 0;
#pragma unroll
        for (int e = 0; e < NE; e++) {
            float s = srow[e];
            if (s > v0) { v1 = v0; i1 = i0; v0 = s; i0 = e; }
            else if (s > v1) { v1 = s; i1 = e; }
        }
        float sum = 0.0f;
#pragma unroll
        for (int e = 0; e < NE; e++) sum += __expf(srow[e] - v0);
        s_rowmax[tid] = v0;
        s_rowinv[tid] = 1.0f / sum;

        float t  = __expf(v1 - v0);
        float w0 = 1.0f / (1.0f + t);
        float w1 = t * w0;

        size_t g = (size_t)blockIdx.x * BM + tid;
        out[2 * g]     = (float)i0;
        out[2 * g + 1] = (float)i1;
        out[OUT_W_OFF + 2 * g]     = w0;
        out[OUT_W_OFF + 2 * g + 1] = w1;
    }
    __syncthreads();

    // ---- phase 2: per-expert partial softmax-prob sums, 4-way row-parallel ----
    {
        const int c = tid >> 6;        // row chunk 0..3 (16 rows each)
        const int e = tid & 63;
        float a = 0.0f;
#pragma unroll 8
        for (int r = c * 16; r < c * 16 + 16; r++) {
            a += __expf(scores[r * SC_STRIDE + e] - s_rowmax[r]) * s_rowinv[r];
        }
        s_p2[c][e] = a;
    }
    __syncthreads();
    if (tid < NE) {
        g_partial[blockIdx.x][tid] =
            s_p2[0][tid] + s_p2[1][tid] + s_p2[2][tid] + s_p2[3][tid];
    }
    __syncthreads();

    // ---- fused finalize: last block to arrive reduces all partials ----
    if (tid == 0) {
        __threadfence();                       // publish g_partial before ticket
        s_rank = atomicAdd(&g_count, 1u);
    }
    __syncthreads();
    if (s_rank == NBLOCKS - 1) {
        __threadfence();                       // acquire all blocks' g_partial
        const int c = tid >> 6;                // chunk 0..3 (128 blocks each)
        const int e = tid & 63;
        float s = 0.0f;
#pragma unroll 4
        for (int b = c * 128; b < c * 128 + 128; b++) s += g_partial[b][e];
        s_p2[c][e] = s;
        __syncthreads();
        if (tid < NE) {
            float t = s_p2[0][tid] + s_p2[1][tid] + s_p2[2][tid] + s_p2[3][tid];
            t *= (1.0f / (float)M_TOTAL);
            s_p2[0][tid] = t * t;
        }
        __syncthreads();
        if (tid == 0) {
            float t = 0.0f;
#pragma unroll
            for (int i = 0; i < NE; i++) t += s_p2[0][i];
            out[OUT_AUX] = (float)NE * t;
            g_count = 0;                       // reset for next graph replay
        }
    }
}

extern "C" void kernel_launch(void* const* d_in, const int* in_sizes, int n_in,
                              void* d_out, int out_size) {
    const float* x = (const float*)d_in[0];   // [4, 8192, 2048] f32
    const float* W = (const float*)d_in[1];   // [64, 2048] f32
    float* out = (float*)d_out;

    router_main<<<NBLOCKS, NTHREADS>>>(x, W, out);
}

// round 13
// speedup vs baseline: 1.2191x; 1.2191x over previous
#include <cuda_runtime.h>
#include <cstdint>

#define DIM        2048
#define NE         64
#define M_TOTAL    32768      // 4 * 8192
#define BM         128
#define BK         32
#define NTHREADS   256
#define NBLOCKS    (M_TOTAL / BM)   // 256
#define NTILES     (DIM / BK)       // 64
#define AS_STRIDE  134        // A tile row stride (floats)
#define BS_STRIDE  68         // B tile row stride (floats), 16B-aligned rows
#define SC_STRIDE  65         // scores row stride (floats) -> conflict-free

// Deterministic per-block partial softmax-prob sums (no atomics on data).
__device__ float g_partial[NBLOCKS][NE];
__device__ unsigned int g_count = 0;   // ticket counter; last block resets -> replay-safe

// out layout (float32): [0,65536) indices, [65536,131072) weights, [131072] aux
#define OUT_W_OFF  (M_TOTAL * 2)
#define OUT_AUX    (M_TOTAL * 4)

typedef unsigned long long u64;

__device__ __forceinline__ u64 pack2(float v) {
    u64 r;
    asm("mov.b64 %0, {%1, %1};" : "=l"(r) : "f"(v));
    return r;
}

__device__ __forceinline__ void fma2(u64& acc, u64 a, u64 b) {
    asm("fma.rn.f32x2 %0, %1, %2, %0;" : "+l"(acc) : "l"(a), "l"(b));
}

// B smem word position for expert e within a k-row:
// e = 8*tx + 4*g + j  ->  word = 32*g + 4*tx + j
// => each of the two per-thread LDS.128 spans banks 0..31 exactly (1 wavefront).
__device__ __forceinline__ int b_word(int e) {
    return ((e & 4) << 3) | ((e >> 3) << 2) | (e & 3);
}

__global__ __launch_bounds__(NTHREADS)
void router_main(const float* __restrict__ x,
                 const float* __restrict__ W,
                 float* __restrict__ out) {
    // smem union: GEMM tiles (As 32x134 + Bs 32x68 = 25.9KB) then scores (128x65 = 33.3KB)
    __shared__ float sm[BM * SC_STRIDE];   // 8320 floats
    __shared__ float s_rowmax[BM];
    __shared__ float s_rowinv[BM];
    __shared__ float s_p2[4][NE];
    __shared__ unsigned int s_rank;

    float* As = sm;                       // [BK][AS_STRIDE]  k-major, m contiguous
    float* Bs = sm + BK * AS_STRIDE;      // [BK][BS_STRIDE]  k-major, swizzled expert order

    const int tid = threadIdx.x;
    const int tx  = tid & 7;              // expert group: 8 experts (tx*8 .. tx*8+7)
    const int ty  = tid >> 3;             // row group: 4 rows = 2 row-pairs (ty*4..+3)

    // G2S index maps (fixed per thread) — identical to R8
    int aRow[4], aKq[4];
#pragma unroll
    for (int i = 0; i < 4; i++) {
        int idx = tid + i * NTHREADS;
        aRow[i] = idx >> 3;
        aKq[i]  = idx & 7;
    }
    int bEr[2], bKq[2], bW[2];
#pragma unroll
    for (int i = 0; i < 2; i++) {
        int idx = tid + i * NTHREADS;
        bEr[i] = idx >> 3;
        bKq[i] = idx & 7;
        bW[i]  = b_word(bEr[i]);
    }

    const float* xblk = x + (size_t)blockIdx.x * BM * DIM;

    // acc[pair i][expert j] : packed f32x2 over rows {ty*4+2i, ty*4+2i+1}, expert tx*8+j
    u64 acc[2][8];
#pragma unroll
    for (int i = 0; i < 2; i++)
#pragma unroll
        for (int j = 0; j < 8; j++) acc[i][j] = 0ULL;

    float4 aReg[4], bReg[2];

    // ---- prologue: load tile 0 into registers, store to smem ----
#pragma unroll
    for (int i = 0; i < 4; i++)
        aReg[i] = *reinterpret_cast<const float4*>(xblk + (size_t)aRow[i] * DIM + aKq[i] * 4);
#pragma unroll
    for (int i = 0; i < 2; i++)
        bReg[i] = *reinterpret_cast<const float4*>(W + (size_t)bEr[i] * DIM + bKq[i] * 4);

#pragma unroll
    for (int i = 0; i < 4; i++) {
        int kb = aKq[i] * 4;
        As[(kb + 0) * AS_STRIDE + aRow[i]] = aReg[i].x;
        As[(kb + 1) * AS_STRIDE + aRow[i]] = aReg[i].y;
        As[(kb + 2) * AS_STRIDE + aRow[i]] = aReg[i].z;
        As[(kb + 3) * AS_STRIDE + aRow[i]] = aReg[i].w;
    }
#pragma unroll
    for (int i = 0; i < 2; i++) {
        int kb = bKq[i] * 4;
        Bs[(kb + 0) * BS_STRIDE + bW[i]] = bReg[i].x;
        Bs[(kb + 1) * BS_STRIDE + bW[i]] = bReg[i].y;
        Bs[(kb + 2) * BS_STRIDE + bW[i]] = bReg[i].z;
        Bs[(kb + 3) * BS_STRIDE + bW[i]] = bReg[i].w;
    }
    __syncthreads();

#pragma unroll 1
    for (int t = 0; t < NTILES; t++) {
        const bool more = t + 1 < NTILES;
        // ---- prefetch next tile into registers (LDGs overlap compute) ----
        if (more) {
            int kn = (t + 1) * BK;
#pragma unroll
            for (int i = 0; i < 4; i++)
                aReg[i] = *reinterpret_cast<const float4*>(xblk + (size_t)aRow[i] * DIM + kn + aKq[i] * 4);
#pragma unroll
            for (int i = 0; i < 2; i++)
                bReg[i] = *reinterpret_cast<const float4*>(W + (size_t)bEr[i] * DIM + kn + bKq[i] * 4);
        }

        // ---- compute current tile ----
#pragma unroll
        for (int kk = 0; kk < BK; kk++) {
            const u64* ar = reinterpret_cast<const u64*>(As + kk * AS_STRIDE + ty * 4);
            u64 a0 = ar[0], a1 = ar[1];
            const float4* bp = reinterpret_cast<const float4*>(Bs + kk * BS_STRIDE + tx * 4);
            float4 bv0 = bp[0];   // experts tx*8 + 0..3
            float4 bv1 = bp[8];   // experts tx*8 + 4..7  (+32 words)
            u64 b0 = pack2(bv0.x), b1 = pack2(bv0.y), b2 = pack2(bv0.z), b3 = pack2(bv0.w);
            u64 b4 = pack2(bv1.x), b5 = pack2(bv1.y), b6 = pack2(bv1.z), b7 = pack2(bv1.w);
            fma2(acc[0][0], a0, b0); fma2(acc[0][1], a0, b1);
            fma2(acc[0][2], a0, b2); fma2(acc[0][3], a0, b3);
            fma2(acc[0][4], a0, b4); fma2(acc[0][5], a0, b5);
            fma2(acc[0][6], a0, b6); fma2(acc[0][7], a0, b7);
            fma2(acc[1][0], a1, b0); fma2(acc[1][1], a1, b1);
            fma2(acc[1][2], a1, b2); fma2(acc[1][3], a1, b3);
            fma2(acc[1][4], a1, b4); fma2(acc[1][5], a1, b5);
            fma2(acc[1][6], a1, b6); fma2(acc[1][7], a1, b7);
        }
        __syncthreads();   // everyone done READING this tile

        // ---- store prefetched tile ----
        if (more) {
#pragma unroll
            for (int i = 0; i < 4; i++) {
                int kb = aKq[i] * 4;
                As[(kb + 0) * AS_STRIDE + aRow[i]] = aReg[i].x;
                As[(kb + 1) * AS_STRIDE + aRow[i]] = aReg[i].y;
                As[(kb + 2) * AS_STRIDE + aRow[i]] = aReg[i].z;
                As[(kb + 3) * AS_STRIDE + aRow[i]] = aReg[i].w;
            }
#pragma unroll
            for (int i = 0; i < 2; i++) {
                int kb = bKq[i] * 4;
                Bs[(kb + 0) * BS_STRIDE + bW[i]] = bReg[i].x;
                Bs[(kb + 1) * BS_STRIDE + bW[i]] = bReg[i].y;
                Bs[(kb + 2) * BS_STRIDE + bW[i]] = bReg[i].z;
                Bs[(kb + 3) * BS_STRIDE + bW[i]] = bReg[i].w;
            }
            __syncthreads();   // tile visible before next compute
        }
    }

    // ---- scatter scores into smem [128][65] ----
#pragma unroll
    for (int i = 0; i < 2; i++) {
        int row0 = ty * 4 + 2 * i;
#pragma unroll
        for (int j = 0; j < 8; j++) {
            int e = tx * 8 + j;
            u64 p = acc[i][j];
            float lo = __uint_as_float((unsigned)(p & 0xffffffffULL));
            float hi = __uint_as_float((unsigned)(p >> 32));
            sm[row0 * SC_STRIDE + e]       = lo;
            sm[(row0 + 1) * SC_STRIDE + e] = hi;
        }
    }
    __syncthreads();

    // ---- phase 1: per-row top-2, weights, row softmax stats ----
    if (tid < BM) {
        const float* srow = sm + tid * SC_STRIDE;
        float v0 = -3.4e38f, v1 = -3.4e38f;
        int i0 = 0, i1 = 0;
#pragma unroll
        for (int e = 0; e < NE; e++) {
            float s = srow[e];
            if (s > v0) { v1 = v0; i1 = i0; v0 = s; i0 = e; }
            else if (s > v1) { v1 = s; i1 = e; }
        }
        float sum = 0.0f;
#pragma unroll
        for (int e = 0; e < NE; e++) sum += __expf(srow[e] - v0);
        s_rowmax[tid] = v0;
        s_rowinv[tid] = 1.0f / sum;

        float t  = __expf(v1 - v0);
        float w0 = 1.0f / (1.0f + t);
        float w1 = t * w0;

        size_t g = (size_t)blockIdx.x * BM + tid;
        out[2 * g]     = (float)i0;
        out[2 * g + 1] = (float)i1;
        out[OUT_W_OFF + 2 * g]     = w0;
        out[OUT_W_OFF + 2 * g + 1] = w1;
    }
    __syncthreads();

    // ---- phase 2: per-expert partial softmax-prob sums, 4-way row-parallel ----
    {
        const int c = tid >> 6;        // row chunk 0..3 (32 rows each)
        const int e = tid & 63;
        float a = 0.0f;
#pragma unroll 8
        for (int r = c * 32; r < c * 32 + 32; r++) {
            a += __expf(sm[r * SC_STRIDE + e] - s_rowmax[r]) * s_rowinv[r];
        }
        s_p2[c][e] = a;
    }
    __syncthreads();
    if (tid < NE) {
        g_partial[blockIdx.x][tid] =
            s_p2[0][tid] + s_p2[1][tid] + s_p2[2][tid] + s_p2[3][tid];
    }
    __syncthreads();

    // ---- fused finalize: last block to arrive reduces all partials ----
    if (tid == 0) {
        __threadfence();                       // publish g_partial before ticket
        s_rank = atomicAdd(&g_count, 1u);
    }
    __syncthreads();
    if (s_rank == NBLOCKS - 1) {
        __threadfence();                       // acquire all blocks' g_partial
        const int c = tid >> 6;                // chunk 0..3 (64 blocks each)
        const int e = tid & 63;
        float s = 0.0f;
#pragma unroll 4
        for (int b = c * 64; b < c * 64 + 64; b++) s += g_partial[b][e];
        s_p2[c][e] = s;
        __syncthreads();
        if (tid < NE) {
            float t = s_p2[0][tid] + s_p2[1][tid] + s_p2[2][tid] + s_p2[3][tid];
            t *= (1.0f / (float)M_TOTAL);
            s_p2[0][tid] = t * t;
        }
        __syncthreads();
        if (tid == 0) {
            float t = 0.0f;
#pragma unroll
            for (int i = 0; i < NE; i++) t += s_p2[0][i];
            out[OUT_AUX] = (float)NE * t;
            g_count = 0;                       // reset for next graph replay
        }
    }
}

extern "C" void kernel_launch(void* const* d_in, const int* in_sizes, int n_in,
                              void* d_out, int out_size) {
    const float* x = (const float*)d_in[0];   // [4, 8192, 2048] f32
    const float* W = (const float*)d_in[1];   // [64, 2048] f32
    float* out = (float*)d_out;

    router_main<<<NBLOCKS, NTHREADS>>>(x, W, out);
}

// round 17
// speedup vs baseline: 1.3267x; 1.0882x over previous
#include <cuda_runtime.h>
#include <cstdint>

#define DIM        2048
#define NE         64
#define M_TOTAL    32768      // 4 * 8192
#define BM         128
#define BK         32
#define NTHREADS   256
#define NBLOCKS    (M_TOTAL / BM)   // 256
#define NTILES     (DIM / BK)       // 64
#define AS_STRIDE  134        // A tile row stride (floats)
#define BS_STRIDE  68         // B tile row stride (floats), 16B-aligned rows
#define SC_STRIDE  65         // scores row stride (floats) -> conflict-free
#define TILE_FLOATS (BK * AS_STRIDE + BK * BS_STRIDE)   // 6464

// Deterministic per-block partial softmax-prob sums (no atomics on data).
__device__ float g_partial[NBLOCKS][NE];
__device__ unsigned int g_count = 0;   // ticket counter; last block resets -> replay-safe

// out layout (float32): [0,65536) indices, [65536,131072) weights, [131072] aux
#define OUT_W_OFF  (M_TOTAL * 2)
#define OUT_AUX    (M_TOTAL * 4)

typedef unsigned long long u64;

__device__ __forceinline__ u64 pack2(float v) {
    u64 r;
    asm("mov.b64 %0, {%1, %1};" : "=l"(r) : "f"(v));
    return r;
}

__device__ __forceinline__ void fma2(u64& acc, u64 a, u64 b) {
    asm("fma.rn.f32x2 %0, %1, %2, %0;" : "+l"(acc) : "l"(a), "l"(b));
}

__global__ __launch_bounds__(NTHREADS)
void router_main(const float* __restrict__ x,
                 const float* __restrict__ W,
                 float* __restrict__ out) {
    // Double-buffered tiles; scores (128x65 = 33.3KB) unions over the 51.7KB tile region.
    __shared__ float tiles[2][TILE_FLOATS];
    __shared__ float s_rowmax[BM];
    __shared__ float s_rowinv[BM];
    __shared__ float s_p2[4][NE];
    __shared__ unsigned int s_rank;

    float* scores = &tiles[0][0];         // [BM][SC_STRIDE]

    const int tid = threadIdx.x;
    const int tx  = tid & 15;             // expert group: 4 experts (tx*4 .. tx*4+3)
    const int ty  = tid >> 4;             // row group: 8 rows = 4 row-pairs

    // G2S index maps (fixed per thread) — identical to R8
    int aRow[4], aKq[4];
#pragma unroll
    for (int i = 0; i < 4; i++) {
        int idx = tid + i * NTHREADS;
        aRow[i] = idx >> 3;
        aKq[i]  = idx & 7;
    }
    int bEr[2], bKq[2];
#pragma unroll
    for (int i = 0; i < 2; i++) {
        int idx = tid + i * NTHREADS;
        bEr[i] = idx >> 3;
        bKq[i] = idx & 7;
    }

    const float* xblk = x + (size_t)blockIdx.x * BM * DIM;

    // acc[pair i][expert j] : packed f32x2 over rows {ty*8+2i, ty*8+2i+1}
    u64 acc[4][4];
#pragma unroll
    for (int i = 0; i < 4; i++)
#pragma unroll
        for (int j = 0; j < 4; j++) acc[i][j] = 0ULL;

    float4 aReg[4], bReg[2];

#define LDG_TILE(koff)                                                                      \
    {                                                                                       \
        _Pragma("unroll")                                                                   \
        for (int i = 0; i < 4; i++)                                                         \
            aReg[i] = *reinterpret_cast<const float4*>(xblk + (size_t)aRow[i] * DIM + (koff) + aKq[i] * 4); \
        _Pragma("unroll")                                                                   \
        for (int i = 0; i < 2; i++)                                                         \
            bReg[i] = *reinterpret_cast<const float4*>(W + (size_t)bEr[i] * DIM + (koff) + bKq[i] * 4);     \
    }

#define STS_TILE(buf)                                                                       \
    {                                                                                       \
        float* As_ = (buf);                                                                 \
        float* Bs_ = (buf) + BK * AS_STRIDE;                                                \
        _Pragma("unroll")                                                                   \
        for (int i = 0; i < 4; i++) {                                                       \
            int kb = aKq[i] * 4;                                                            \
            As_[(kb + 0) * AS_STRIDE + aRow[i]] = aReg[i].x;                                \
            As_[(kb + 1) * AS_STRIDE + aRow[i]] = aReg[i].y;                                \
            As_[(kb + 2) * AS_STRIDE + aRow[i]] = aReg[i].z;                                \
            As_[(kb + 3) * AS_STRIDE + aRow[i]] = aReg[i].w;                                \
        }                                                                                   \
        _Pragma("unroll")                                                                   \
        for (int i = 0; i < 2; i++) {                                                       \
            int kb = bKq[i] * 4;                                                            \
            Bs_[(kb + 0) * BS_STRIDE + bEr[i]] = bReg[i].x;                                 \
            Bs_[(kb + 1) * BS_STRIDE + bEr[i]] = bReg[i].y;                                 \
            Bs_[(kb + 2) * BS_STRIDE + bEr[i]] = bReg[i].z;                                 \
            Bs_[(kb + 3) * BS_STRIDE + bEr[i]] = bReg[i].w;                                 \
        }                                                                                   \
    }

    // ---- prologue: tile 0 into buffer 0 ----
    LDG_TILE(0);
    STS_TILE(&tiles[0][0]);
    __syncthreads();

    int p = 0;
#pragma unroll 1
    for (int t = 0; t < NTILES; t++) {
        const bool more = t + 1 < NTILES;
        if (more) LDG_TILE((t + 1) * BK);   // overlap LDGs with compute

        // ---- compute current tile from buffer p ----
        {
            const float* As = &tiles[p][0];
            const float* Bs = &tiles[p][0] + BK * AS_STRIDE;
#pragma unroll
            for (int kk = 0; kk < BK; kk++) {
                const u64* ar = reinterpret_cast<const u64*>(As + kk * AS_STRIDE + ty * 8);
                u64 a0 = ar[0], a1 = ar[1], a2 = ar[2], a3 = ar[3];
                float4 bv = *reinterpret_cast<const float4*>(Bs + kk * BS_STRIDE + tx * 4);
                u64 b0 = pack2(bv.x);
                u64 b1 = pack2(bv.y);
                u64 b2 = pack2(bv.z);
                u64 b3 = pack2(bv.w);
                fma2(acc[0][0], a0, b0); fma2(acc[0][1], a0, b1);
                fma2(acc[0][2], a0, b2); fma2(acc[0][3], a0, b3);
                fma2(acc[1][0], a1, b0); fma2(acc[1][1], a1, b1);
                fma2(acc[1][2], a1, b2); fma2(acc[1][3], a1, b3);
                fma2(acc[2][0], a2, b0); fma2(acc[2][1], a2, b1);
                fma2(acc[2][2], a2, b2); fma2(acc[2][3], a2, b3);
                fma2(acc[3][0], a3, b0); fma2(acc[3][1], a3, b1);
                fma2(acc[3][2], a3, b2); fma2(acc[3][3], a3, b3);
            }
        }

        // ---- store prefetched tile into the other buffer (its readers finished
        //      at the barrier that ended iteration t-1) ----
        if (more) STS_TILE(&tiles[p ^ 1][0]);

        __syncthreads();   // one barrier per tile: readers of p done, writes to p^1 visible
        p ^= 1;
    }

    // ---- scatter scores into smem [128][65] (tile region; barrier above protects) ----
#pragma unroll
    for (int i = 0; i < 4; i++) {
        int row0 = ty * 8 + 2 * i;
#pragma unroll
        for (int j = 0; j < 4; j++) {
            int e = tx * 4 + j;
            u64 pk = acc[i][j];
            float lo = __uint_as_float((unsigned)(pk & 0xffffffffULL));
            float hi = __uint_as_float((unsigned)(pk >> 32));
            scores[row0 * SC_STRIDE + e]       = lo;
            scores[(row0 + 1) * SC_STRIDE + e] = hi;
        }
    }
    __syncthreads();

    // ---- phase 1: per-row top-2, weights, row softmax stats ----
    if (tid < BM) {
        const float* srow = scores + tid * SC_STRIDE;
        float v0 = -3.4e38f, v1 = -3.4e38f;
        int i0 = 0, i1 = 0;
#pragma unroll
        for (int e = 0; e < NE; e++) {
            float s = srow[e];
            if (s > v0) { v1 = v0; i1 = i0; v0 = s; i0 = e; }
            else if (s > v1) { v1 = s; i1 = e; }
        }
        float sum = 0.0f;
#pragma unroll
        for (int e = 0; e < NE; e++) sum += __expf(srow[e] - v0);
        s_rowmax[tid] = v0;
        s_rowinv[tid] = 1.0f / sum;

        float t  = __expf(v1 - v0);
        float w0 = 1.0f / (1.0f + t);
        float w1 = t * w0;

        size_t g = (size_t)blockIdx.x * BM + tid;
        out[2 * g]     = (float)i0;
        out[2 * g + 1] = (float)i1;
        out[OUT_W_OFF + 2 * g]     = w0;
        out[OUT_W_OFF + 2 * g + 1] = w1;
    }
    __syncthreads();

    // ---- phase 2: per-expert partial softmax-prob sums, 4-way row-parallel ----
    {
        const int c = tid >> 6;        // row chunk 0..3 (32 rows each)
        const int e = tid & 63;
        float a = 0.0f;
#pragma unroll 8
        for (int r = c * 32; r < c * 32 + 32; r++) {
            a += __expf(scores[r * SC_STRIDE + e] - s_rowmax[r]) * s_rowinv[r];
        }
        s_p2[c][e] = a;
    }
    __syncthreads();
    if (tid < NE) {
        g_partial[blockIdx.x][tid] =
            s_p2[0][tid] + s_p2[1][tid] + s_p2[2][tid] + s_p2[3][tid];
    }
    __syncthreads();

    // ---- fused finalize: last block to arrive reduces all partials ----
    if (tid == 0) {
        __threadfence();                       // publish g_partial before ticket
        s_rank = atomicAdd(&g_count, 1u);
    }
    __syncthreads();
    if (s_rank == NBLOCKS - 1) {
        __threadfence();                       // acquire all blocks' g_partial
        const int c = tid >> 6;                // chunk 0..3 (64 blocks each)
        const int e = tid & 63;
        float s = 0.0f;
#pragma unroll 4
        for (int b = c * 64; b < c * 64 + 64; b++) s += g_partial[b][e];
        s_p2[c][e] = s;
        __syncthreads();
        if (tid < NE) {
            float t = s_p2[0][tid] + s_p2[1][tid] + s_p2[2][tid] + s_p2[3][tid];
            t *= (1.0f / (float)M_TOTAL);
            s_p2[0][tid] = t * t;
        }
        __syncthreads();
        if (tid == 0) {
            float t = 0.0f;
#pragma unroll
            for (int i = 0; i < NE; i++) t += s_p2[0][i];
            out[OUT_AUX] = (float)NE * t;
            g_count = 0;                       // reset for next graph replay
        }
    }
}

extern "C" void kernel_launch(void* const* d_in, const int* in_sizes, int n_in,
                              void* d_out, int out_size) {
    const float* x = (const float*)d_in[0];   // [4, 8192, 2048] f32
    const float* W = (const float*)d_in[1];   // [64, 2048] f32
    float* out = (float*)d_out;

    router_main<<<NBLOCKS, NTHREADS>>>(x, W, out);
}